// round 4
// baseline (speedup 1.0000x reference)
#include <cuda_runtime.h>
#include <cuda_bf16.h>
#include <cuda_fp8.h>
#include <stdint.h>

#define SEQ 80
#define EMB 100
#define VOCAB 10000
#define BMAX 16384
#define WPAD 80   // fp8 W^T row stride (bytes): 5r mod 8 distinct -> conflict-free ldmatrix

// Precomputed emb @ Wx0 + b0 : [VOCAB, 64] fp32 (2.56 MB, L2-resident)
__device__ float g_embW0[VOCAB * 64];
// Transposed tokens [SEQ][B]
__device__ int g_tokT[SEQ * BMAX];

#define EMBW_BLOCKS 313   // 32 vocab rows per block

// ---------------------------------------------------------------------------
// Prep (fused): blocks [0,313) -> embW0 = emb@Wx0 + b0 ; rest -> token transpose
// ---------------------------------------------------------------------------
__global__ void __launch_bounds__(256) prep_kernel(const float* __restrict__ emb,
                                                   const float* __restrict__ Wx0,
                                                   const float* __restrict__ b0,
                                                   const int*   __restrict__ tokens,
                                                   int B) {
    if (blockIdx.x >= EMBW_BLOCKS) {
        int b = (blockIdx.x - EMBW_BLOCKS) * 256 + threadIdx.x;
        if (b < B) {
            #pragma unroll
            for (int s = 0; s < SEQ; ++s)
                g_tokT[s * B + b] = tokens[b * SEQ + s];
        }
        return;
    }
    __shared__ float sW[EMB * 64];
    __shared__ float sE[32 * EMB];
    int tid = threadIdx.x;
    for (int i = tid; i < EMB * 64; i += 256) sW[i] = Wx0[i];
    int vbase = blockIdx.x * 32;
    for (int i = tid; i < 32 * EMB; i += 256) {
        int r = vbase + i / EMB;
        sE[i] = emb[(r < VOCAB ? r : 0) * EMB + i % EMB];
    }
    __syncthreads();

    int trow = tid >> 3, tcol = tid & 7;   // 32 rows x 8 unit-groups
    float a[8];
    *reinterpret_cast<float4*>(a)     = *reinterpret_cast<const float4*>(b0 + tcol * 8);
    *reinterpret_cast<float4*>(a + 4) = *reinterpret_cast<const float4*>(b0 + tcol * 8 + 4);
    const float* e = sE + trow * EMB;
    const float4* sW4 = reinterpret_cast<const float4*>(sW);
    #pragma unroll 10
    for (int k = 0; k < EMB; ++k) {
        float ev = e[k];
        float4 w0 = sW4[k * 16 + tcol * 2];
        float4 w1 = sW4[k * 16 + tcol * 2 + 1];
        a[0] += ev * w0.x; a[1] += ev * w0.y; a[2] += ev * w0.z; a[3] += ev * w0.w;
        a[4] += ev * w1.x; a[5] += ev * w1.y; a[6] += ev * w1.z; a[7] += ev * w1.w;
    }
    int v = vbase + trow;
    if (v < VOCAB) {
        *reinterpret_cast<float4*>(g_embW0 + v * 64 + tcol * 8)     = *reinterpret_cast<float4*>(a);
        *reinterpret_cast<float4*>(g_embW0 + v * 64 + tcol * 8 + 4) = *reinterpret_cast<float4*>(a + 4);
    }
}

// ---------------------------------------------------------------------------
// PTX helpers
// ---------------------------------------------------------------------------
__device__ __forceinline__ void mma_fp8(float& d0, float& d1, float& d2, float& d3,
                                        uint32_t a0, uint32_t a1, uint32_t a2, uint32_t a3,
                                        uint32_t b0, uint32_t b1) {
    asm("mma.sync.aligned.m16n8k32.row.col.f32.e4m3.e4m3.f32 "
        "{%0,%1,%2,%3},{%4,%5,%6,%7},{%8,%9},{%0,%1,%2,%3};"
        : "+f"(d0), "+f"(d1), "+f"(d2), "+f"(d3)
        : "r"(a0), "r"(a1), "r"(a2), "r"(a3), "r"(b0), "r"(b1));
}

__device__ __forceinline__ void ldsm4(uint32_t& x, uint32_t& y, uint32_t& z, uint32_t& w,
                                      uint32_t saddr) {
    asm volatile("ldmatrix.sync.aligned.m8n8.x4.shared.b16 {%0,%1,%2,%3}, [%4];"
                 : "=r"(x), "=r"(y), "=r"(z), "=r"(w) : "r"(saddr));
}

// pack(lo, hi) -> f16x2 (lo in low half)
__device__ __forceinline__ uint32_t f16x2_of(float lo, float hi) {
    uint32_t r;
    asm("cvt.rn.f16x2.f32 %0, %1, %2;" : "=r"(r) : "f"(hi), "f"(lo));
    return r;
}

__device__ __forceinline__ uint32_t tanh_f16x2(uint32_t v) {
    uint32_t r;
    asm("tanh.approx.f16x2 %0, %1;" : "=r"(r) : "r"(v));
    return r;
}

// two f16x2 -> 4 e4m3 bytes [a.lo, a.hi, b.lo, b.hi]
__device__ __forceinline__ uint32_t pack_e4m3(uint32_t fa, uint32_t fb) {
    uint32_t r;
    asm("{\n\t"
        ".reg .b16 lo, hi;\n\t"
        "cvt.rn.satfinite.e4m3x2.f16x2 lo, %1;\n\t"
        "cvt.rn.satfinite.e4m3x2.f16x2 hi, %2;\n\t"
        "mov.b32 %0, {lo, hi};\n\t"
        "}" : "=r"(r) : "r"(fa), "r"(fb));
    return r;
}

__device__ __forceinline__ float fast_tanh(float x) {
    float y;
    asm("tanh.approx.f32 %0, %1;" : "=f"(y) : "f"(x));
    return y;
}

// acc[32] (fp32 pre-act) -> h[8] fp8 A-fragments (tanh applied)
__device__ __forceinline__ void tanh_to_fp8_frags(const float* acc, uint32_t* h) {
    uint32_t t0[8], t1[8];
    #pragma unroll
    for (int nt = 0; nt < 8; ++nt) {
        t0[nt] = tanh_f16x2(f16x2_of(acc[2 * nt],      acc[2 * nt + 1]));
        t1[nt] = tanh_f16x2(f16x2_of(acc[16 + 2 * nt], acc[16 + 2 * nt + 1]));
    }
    #pragma unroll
    for (int c = 0; c < 2; ++c) {
        h[c * 4 + 0] = pack_e4m3(t0[4 * c],     t0[4 * c + 1]);
        h[c * 4 + 1] = pack_e4m3(t1[4 * c],     t1[4 * c + 1]);
        h[c * 4 + 2] = pack_e4m3(t0[4 * c + 2], t0[4 * c + 3]);
        h[c * 4 + 3] = pack_e4m3(t1[4 * c + 2], t1[4 * c + 3]);
    }
}

// ---------------------------------------------------------------------------
// Kernel 2: fp8 recurrence. 4 warps/CTA, M=16 rows/warp, grid = B/64.
// Unit-dimension bit-permutation makes D->A repack free; weights permuted
// at smem-fill time: Wsm[n][k] = e4m3(W[p(k)][n]).
// ---------------------------------------------------------------------------
__global__ void __launch_bounds__(128, 3) rnn_kernel(
    const float* __restrict__ Wh0,
    const float* __restrict__ Wx1,
    const float* __restrict__ Wh1,
    const float* __restrict__ b1,
    const float* __restrict__ Wout,
    const float* __restrict__ bout,
    float*       __restrict__ out,
    int B) {
    __shared__ __align__(16) uint8_t sW8[3 * 64 * WPAD];  // Wh0^T, Wx1^T, Wh1^T (fp8)

    {
        const float* Ws[3] = {Wh0, Wx1, Wh1};
        #pragma unroll
        for (int w = 0; w < 3; ++w) {
            for (int i = threadIdx.x; i < 64 * 64; i += 128) {
                int n = i >> 6, kp = i & 63;
                // k-position kp holds unit p(kp)
                int p = (kp & 0x30) | ((kp & 0x02) << 2) | ((kp & 0x0C) >> 1) | (kp & 0x01);
                __nv_fp8_e4m3 q(Ws[w][p * 64 + n]);
                sW8[w * 64 * WPAD + n * WPAD + kp] = q.__x;
            }
        }
    }
    __syncthreads();

    const int lane = threadIdx.x & 31;
    const int warp = threadIdx.x >> 5;
    const int g  = lane >> 2;   // row-in-tile
    const int tq = lane & 3;    // column pair
    const int base = (blockIdx.x * 4 + warp) * 16;

    int rraw[2], rc[2];
    #pragma unroll
    for (int i = 0; i < 2; ++i) {
        rraw[i] = base + g + 8 * i;
        rc[i]   = rraw[i] < B ? rraw[i] : (B - 1);
    }

    // ldmatrix lane term: quad q = lane>>3 selects (ntB?, b1?) tile; r = row in tile
    const int q = lane >> 3, r = lane & 7;
    const uint32_t laneterm = (uint32_t)((q >> 1) * (8 * WPAD) + r * WPAD + (q & 1) * 16);
    uint32_t swb = (uint32_t)__cvta_generic_to_shared(sW8);
    const uint32_t aW0 = swb + laneterm;
    const uint32_t aW1 = aW0 + 64 * WPAD;
    const uint32_t aW2 = aW1 + 64 * WPAD;

    float b1f[16];
    #pragma unroll
    for (int nt = 0; nt < 8; ++nt) {
        b1f[nt * 2]     = b1[nt * 8 + tq * 2];
        b1f[nt * 2 + 1] = b1[nt * 8 + tq * 2 + 1];
    }

    float    accA[32], accB[32];
    uint32_t h0f[8], h1f[8];
    #pragma unroll
    for (int i = 0; i < 8; ++i) { h0f[i] = 0u; h1f[i] = 0u; }

    // preload gather for step 0
    #pragma unroll
    for (int i = 0; i < 2; ++i) {
        int tok = g_tokT[rc[i]];
        const float2* src = reinterpret_cast<const float2*>(g_embW0 + tok * 64) + tq;
        #pragma unroll
        for (int nt = 0; nt < 8; ++nt) {
            float2 v = src[nt * 4];
            accA[i * 16 + nt * 2]     = v.x;
            accA[i * 16 + nt * 2 + 1] = v.y;
        }
    }

    #pragma unroll 1
    for (int ts = 0; ts < SEQ; ++ts) {
        int tsn = (ts + 1 < SEQ) ? ts + 1 : SEQ - 1;
        int tkn[2];
        #pragma unroll
        for (int i = 0; i < 2; ++i) tkn[i] = g_tokT[tsn * B + rc[i]];

        // accB = b1
        #pragma unroll
        for (int nt = 0; nt < 8; ++nt) {
            accB[nt * 2]          = b1f[nt * 2];
            accB[nt * 2 + 1]      = b1f[nt * 2 + 1];
            accB[16 + nt * 2]     = b1f[nt * 2];
            accB[16 + nt * 2 + 1] = b1f[nt * 2 + 1];
        }

        // interleaved: accA += h0 @ Wh0 ; accB += h1 @ Wh1
        #pragma unroll
        for (int c = 0; c < 2; ++c) {
            #pragma unroll
            for (int ntp = 0; ntp < 4; ++ntp) {
                uint32_t off = (uint32_t)(ntp * (16 * WPAD) + 32 * c);
                int nA = 2 * ntp, nB = 2 * ntp + 1;
                uint32_t x0, y0, z0, w0, x2, y2, z2, w2;
                ldsm4(x0, y0, z0, w0, aW0 + off);
                ldsm4(x2, y2, z2, w2, aW2 + off);
                mma_fp8(accA[nA*2], accA[nA*2+1], accA[16+nA*2], accA[16+nA*2+1],
                        h0f[c*4+0], h0f[c*4+1], h0f[c*4+2], h0f[c*4+3], x0, y0);
                mma_fp8(accA[nB*2], accA[nB*2+1], accA[16+nB*2], accA[16+nB*2+1],
                        h0f[c*4+0], h0f[c*4+1], h0f[c*4+2], h0f[c*4+3], z0, w0);
                mma_fp8(accB[nA*2], accB[nA*2+1], accB[16+nA*2], accB[16+nA*2+1],
                        h1f[c*4+0], h1f[c*4+1], h1f[c*4+2], h1f[c*4+3], x2, y2);
                mma_fp8(accB[nB*2], accB[nB*2+1], accB[16+nB*2], accB[16+nB*2+1],
                        h1f[c*4+0], h1f[c*4+1], h1f[c*4+2], h1f[c*4+3], z2, w2);
            }
        }

        // h0 = tanh(accA) -> fp8 frags
        tanh_to_fp8_frags(accA, h0f);

        // prefetch next-step gather into accA (covers L2 latency over layer 1)
        #pragma unroll
        for (int i = 0; i < 2; ++i) {
            const float2* src = reinterpret_cast<const float2*>(g_embW0 + tkn[i] * 64) + tq;
            #pragma unroll
            for (int nt = 0; nt < 8; ++nt) {
                float2 v = src[nt * 4];
                accA[i * 16 + nt * 2]     = v.x;
                accA[i * 16 + nt * 2 + 1] = v.y;
            }
        }

        // accB += h0new @ Wx1
        #pragma unroll
        for (int c = 0; c < 2; ++c) {
            #pragma unroll
            for (int ntp = 0; ntp < 4; ++ntp) {
                uint32_t off = (uint32_t)(ntp * (16 * WPAD) + 32 * c);
                int nA = 2 * ntp, nB = 2 * ntp + 1;
                uint32_t x1, y1, z1, w1;
                ldsm4(x1, y1, z1, w1, aW1 + off);
                mma_fp8(accB[nA*2], accB[nA*2+1], accB[16+nA*2], accB[16+nA*2+1],
                        h0f[c*4+0], h0f[c*4+1], h0f[c*4+2], h0f[c*4+3], x1, y1);
                mma_fp8(accB[nB*2], accB[nB*2+1], accB[16+nB*2], accB[16+nB*2+1],
                        h0f[c*4+0], h0f[c*4+1], h0f[c*4+2], h0f[c*4+3], z1, w1);
            }
        }

        // h1 = tanh(accB) -> fp8 frags
        tanh_to_fp8_frags(accB, h1f);
    }

    // ---- head: sigmoid(tanh(accB) @ Wout + bout), fp32 tanh on final step ----
    float wo[16];
    #pragma unroll
    for (int nt = 0; nt < 8; ++nt) {
        float2 v = *reinterpret_cast<const float2*>(Wout + nt * 8 + tq * 2);
        wo[nt * 2] = v.x; wo[nt * 2 + 1] = v.y;
    }
    float bo = bout[0];
    #pragma unroll
    for (int i = 0; i < 2; ++i) {
        float s = 0.f;
        #pragma unroll
        for (int nt = 0; nt < 8; ++nt) {
            s += fast_tanh(accB[i * 16 + nt * 2])     * wo[nt * 2];
            s += fast_tanh(accB[i * 16 + nt * 2 + 1]) * wo[nt * 2 + 1];
        }
        s += __shfl_xor_sync(0xffffffffu, s, 1);
        s += __shfl_xor_sync(0xffffffffu, s, 2);
        if (tq == 0 && rraw[i] < B)
            out[rraw[i]] = 1.0f / (1.0f + __expf(-(s + bo)));
    }
}

// ---------------------------------------------------------------------------
extern "C" void kernel_launch(void* const* d_in, const int* in_sizes, int n_in,
                              void* d_out, int out_size) {
    const int*   tokens = (const int*)  d_in[0];
    const float* emb    = (const float*)d_in[1];
    const float* Wx0    = (const float*)d_in[2];
    const float* Wh0    = (const float*)d_in[3];
    const float* b0     = (const float*)d_in[4];
    const float* Wx1    = (const float*)d_in[5];
    const float* Wh1    = (const float*)d_in[6];
    const float* b1     = (const float*)d_in[7];
    const float* Wout   = (const float*)d_in[8];
    const float* bout   = (const float*)d_in[9];
    float* out = (float*)d_out;

    int B = in_sizes[0] / SEQ;
    if (B > BMAX) B = BMAX;

    int prep_blocks = EMBW_BLOCKS + (B + 255) / 256;
    prep_kernel<<<prep_blocks, 256>>>(emb, Wx0, b0, tokens, B);

    int nblocks = (B + 63) / 64;
    rnn_kernel<<<nblocks, 128>>>(Wh0, Wx1, Wh1, b1, Wout, bout, out, B);
}

// round 5
// speedup vs baseline: 1.1092x; 1.1092x over previous
#include <cuda_runtime.h>
#include <cuda_fp8.h>
#include <stdint.h>

#define SEQ 80
#define EMB 100
#define VOCAB 10000
#define BMAX 16384

// Precomputed emb @ Wx0 + b0, columns stored permuted: unit j -> slot s(j)
__device__ float g_embW0[VOCAB * 64];
// Transposed tokens [SEQ][B]
__device__ int g_tokT[SEQ * BMAX];
// Weight B-fragments, fp8, register-file layout: word = (m*8+nt)*128 + lane*4 + (u*2+c)
__device__ uint32_t g_wfrag[3 * 8 * 32 * 4];

#define EMBW_BLOCKS 313
#define WFRAG_BLOCKS 3

// unit held at k-position kp (same permutation as R4, empirically verified)
__host__ __device__ __forceinline__ int punit(int kp) {
    return (kp & 0x30) | ((kp & 2) << 2) | ((kp & 0xC) >> 1) | (kp & 1);
}
// storage slot of unit j in permuted embW0 row: lane(tq) reads contiguous 16B chunks
__host__ __device__ __forceinline__ int sidx(int j) {
    int nt = j >> 3, tq = (j >> 1) & 3, e = j & 1;
    return (nt >> 1) * 16 + tq * 4 + (nt & 1) * 2 + e;
}

// ---------------------------------------------------------------------------
// Prep (fused):
//  blocks [0,313): embW0 = emb@Wx0 + b0 (permuted columns), 32 vocab rows/block
//  blocks [313,316): weight fragment build (one matrix each)
//  rest: token transpose
// ---------------------------------------------------------------------------
__global__ void __launch_bounds__(256) prep_kernel(const float* __restrict__ emb,
                                                   const float* __restrict__ Wx0,
                                                   const float* __restrict__ b0,
                                                   const float* __restrict__ Wh0,
                                                   const float* __restrict__ Wx1,
                                                   const float* __restrict__ Wh1,
                                                   const int*   __restrict__ tokens,
                                                   int B) {
    int tid = threadIdx.x;
    if (blockIdx.x < EMBW_BLOCKS) {
        __shared__ float sW[EMB * 64];
        __shared__ float sE[32 * EMB];
        for (int i = tid; i < EMB * 64; i += 256) sW[i] = Wx0[i];
        int vbase = blockIdx.x * 32;
        for (int i = tid; i < 32 * EMB; i += 256) {
            int r = vbase + i / EMB;
            sE[i] = emb[(r < VOCAB ? r : 0) * EMB + i % EMB];
        }
        __syncthreads();

        int tcol = tid & 15;   // 4 units each
        int trow = tid >> 4;   // rows trow, trow+16
        float a0[4], a1[4];
        *reinterpret_cast<float4*>(a0) = *reinterpret_cast<const float4*>(b0 + tcol * 4);
        *reinterpret_cast<float4*>(a1) = *reinterpret_cast<float4*>(a0);
        const float* e0 = sE + trow * EMB;
        const float* e1 = sE + (trow + 16) * EMB;
        const float4* sW4 = reinterpret_cast<const float4*>(sW);
        #pragma unroll 10
        for (int k = 0; k < EMB; ++k) {
            float4 w = sW4[k * 16 + tcol];
            float ev0 = e0[k], ev1 = e1[k];
            a0[0] += ev0 * w.x; a0[1] += ev0 * w.y; a0[2] += ev0 * w.z; a0[3] += ev0 * w.w;
            a1[0] += ev1 * w.x; a1[1] += ev1 * w.y; a1[2] += ev1 * w.z; a1[3] += ev1 * w.w;
        }
        int v0 = vbase + trow, v1 = vbase + trow + 16;
        #pragma unroll
        for (int jj = 0; jj < 4; ++jj) {
            int s = sidx(tcol * 4 + jj);
            if (v0 < VOCAB) g_embW0[v0 * 64 + s] = a0[jj];
            if (v1 < VOCAB) g_embW0[v1 * 64 + s] = a1[jj];
        }
        return;
    }
    if (blockIdx.x < EMBW_BLOCKS + WFRAG_BLOCKS) {
        int m = blockIdx.x - EMBW_BLOCKS;
        const float* W = (m == 0) ? Wh0 : (m == 1) ? Wx1 : Wh1;
        for (int t = tid; t < 1024; t += 256) {
            int lane = t & 31, r = t >> 5;
            int nt = r >> 2, u = (r >> 1) & 1, c = r & 1;
            int n = nt * 8 + (lane >> 2);
            uint32_t word = 0;
            #pragma unroll
            for (int bB = 0; bB < 4; ++bB) {
                int kp = c * 32 + u * 16 + (lane & 3) * 4 + bB;
                __nv_fp8_e4m3 q(W[punit(kp) * 64 + n]);
                word |= (uint32_t)q.__x << (8 * bB);
            }
            g_wfrag[(m * 8 + nt) * 128 + lane * 4 + (u * 2 + c)] = word;
        }
        return;
    }
    int b = (blockIdx.x - EMBW_BLOCKS - WFRAG_BLOCKS) * 256 + tid;
    if (b < B) {
        #pragma unroll
        for (int s = 0; s < SEQ; ++s)
            g_tokT[s * B + b] = tokens[b * SEQ + s];
    }
}

// ---------------------------------------------------------------------------
// PTX helpers
// ---------------------------------------------------------------------------
__device__ __forceinline__ void mma_fp8(float& d0, float& d1, float& d2, float& d3,
                                        uint32_t a0, uint32_t a1, uint32_t a2, uint32_t a3,
                                        uint32_t b0, uint32_t b1) {
    asm("mma.sync.aligned.m16n8k32.row.col.f32.e4m3.e4m3.f32 "
        "{%0,%1,%2,%3},{%4,%5,%6,%7},{%8,%9},{%0,%1,%2,%3};"
        : "+f"(d0), "+f"(d1), "+f"(d2), "+f"(d3)
        : "r"(a0), "r"(a1), "r"(a2), "r"(a3), "r"(b0), "r"(b1));
}

// first-use variant: D = A@B + C with C = {c0,c1,c0,c1} (folds bias, saves MOVs)
__device__ __forceinline__ void mma_fp8_c(float& d0, float& d1, float& d2, float& d3,
                                          uint32_t a0, uint32_t a1, uint32_t a2, uint32_t a3,
                                          uint32_t b0, uint32_t b1, float c0, float c1) {
    asm("mma.sync.aligned.m16n8k32.row.col.f32.e4m3.e4m3.f32 "
        "{%0,%1,%2,%3},{%4,%5,%6,%7},{%8,%9},{%10,%11,%10,%11};"
        : "=f"(d0), "=f"(d1), "=f"(d2), "=f"(d3)
        : "r"(a0), "r"(a1), "r"(a2), "r"(a3), "r"(b0), "r"(b1), "f"(c0), "f"(c1));
}

__device__ __forceinline__ uint32_t f16x2_of(float lo, float hi) {
    uint32_t r;
    asm("cvt.rn.f16x2.f32 %0, %1, %2;" : "=r"(r) : "f"(hi), "f"(lo));
    return r;
}

__device__ __forceinline__ uint32_t tanh_f16x2(uint32_t v) {
    uint32_t r;
    asm("tanh.approx.f16x2 %0, %1;" : "=r"(r) : "r"(v));
    return r;
}

__device__ __forceinline__ uint32_t pack_e4m3(uint32_t fa, uint32_t fb) {
    uint32_t r;
    asm("{\n\t"
        ".reg .b16 lo, hi;\n\t"
        "cvt.rn.satfinite.e4m3x2.f16x2 lo, %1;\n\t"
        "cvt.rn.satfinite.e4m3x2.f16x2 hi, %2;\n\t"
        "mov.b32 %0, {lo, hi};\n\t"
        "}" : "=r"(r) : "r"(fa), "r"(fb));
    return r;
}

__device__ __forceinline__ float fast_tanh(float x) {
    float y;
    asm("tanh.approx.f32 %0, %1;" : "=f"(y) : "f"(x));
    return y;
}

// acc[32] (fp32 pre-act) -> h[8] fp8 A-fragments (tanh applied)
__device__ __forceinline__ void tanh_to_fp8_frags(const float* acc, uint32_t* h) {
    uint32_t t0[8], t1[8];
    #pragma unroll
    for (int nt = 0; nt < 8; ++nt) {
        t0[nt] = tanh_f16x2(f16x2_of(acc[2 * nt],      acc[2 * nt + 1]));
        t1[nt] = tanh_f16x2(f16x2_of(acc[16 + 2 * nt], acc[16 + 2 * nt + 1]));
    }
    #pragma unroll
    for (int c = 0; c < 2; ++c) {
        h[c * 4 + 0] = pack_e4m3(t0[4 * c],     t0[4 * c + 1]);
        h[c * 4 + 1] = pack_e4m3(t1[4 * c],     t1[4 * c + 1]);
        h[c * 4 + 2] = pack_e4m3(t0[4 * c + 2], t0[4 * c + 3]);
        h[c * 4 + 3] = pack_e4m3(t1[4 * c + 2], t1[4 * c + 3]);
    }
}

// ---------------------------------------------------------------------------
// Kernel 2: fp8 recurrence. ONE warp per CTA, M=16 rows, grid = B/16 = 1024.
// All weight fragments live in registers (96 regs); no smem, no syncs.
// ---------------------------------------------------------------------------
__global__ void __launch_bounds__(32, 8) rnn_kernel(
    const float* __restrict__ b1,
    const float* __restrict__ Wout,
    const float* __restrict__ bout,
    float*       __restrict__ out,
    int B) {
    const int lane = threadIdx.x;
    const int g  = lane >> 2;
    const int tq = lane & 3;
    const int base = blockIdx.x * 16;

    int rraw[2], rc[2];
    #pragma unroll
    for (int i = 0; i < 2; ++i) {
        rraw[i] = base + g + 8 * i;
        rc[i]   = rraw[i] < B ? rraw[i] : (B - 1);
    }

    // ---- load all weight B-fragments into registers ----
    uint32_t wf[96];   // [m][nt][u*2+c]
    {
        const uint4* wp = reinterpret_cast<const uint4*>(g_wfrag);
        #pragma unroll
        for (int m = 0; m < 3; ++m) {
            #pragma unroll
            for (int nt = 0; nt < 8; ++nt) {
                uint4 v = wp[(m * 8 + nt) * 32 + lane];
                wf[m * 32 + nt * 4 + 0] = v.x;
                wf[m * 32 + nt * 4 + 1] = v.y;
                wf[m * 32 + nt * 4 + 2] = v.z;
                wf[m * 32 + nt * 4 + 3] = v.w;
            }
        }
    }

    float b1f[16];
    #pragma unroll
    for (int nt = 0; nt < 8; ++nt) {
        b1f[nt * 2]     = b1[nt * 8 + tq * 2];
        b1f[nt * 2 + 1] = b1[nt * 8 + tq * 2 + 1];
    }

    float    accA[32], accB[32];
    uint32_t h0f[8], h1f[8];
    #pragma unroll
    for (int i = 0; i < 8; ++i) { h0f[i] = 0u; h1f[i] = 0u; }

    // preload gather for step 0 (contiguous 64B per lane, permuted layout)
    #pragma unroll
    for (int i = 0; i < 2; ++i) {
        int tok = g_tokT[rc[i]];
        const float* rowp = g_embW0 + tok * 64 + tq * 4;
        #pragma unroll
        for (int f = 0; f < 4; ++f) {
            float4 v = *reinterpret_cast<const float4*>(rowp + f * 16);
            accA[i * 16 + f * 4 + 0] = v.x;
            accA[i * 16 + f * 4 + 1] = v.y;
            accA[i * 16 + f * 4 + 2] = v.z;
            accA[i * 16 + f * 4 + 3] = v.w;
        }
    }

    #pragma unroll 1
    for (int ts = 0; ts < SEQ; ++ts) {
        int tsn = (ts + 1 < SEQ) ? ts + 1 : SEQ - 1;
        int tkn[2];
        #pragma unroll
        for (int i = 0; i < 2; ++i) tkn[i] = g_tokT[tsn * B + rc[i]];

        // interleaved: accA += h0 @ Wh0 ; accB = b1 + h1 @ Wh1
        #pragma unroll
        for (int nt = 0; nt < 8; ++nt) {
            mma_fp8(accA[nt*2], accA[nt*2+1], accA[16+nt*2], accA[16+nt*2+1],
                    h0f[0], h0f[1], h0f[2], h0f[3],
                    wf[nt*4 + 0], wf[nt*4 + 2]);
            mma_fp8_c(accB[nt*2], accB[nt*2+1], accB[16+nt*2], accB[16+nt*2+1],
                      h1f[0], h1f[1], h1f[2], h1f[3],
                      wf[64 + nt*4 + 0], wf[64 + nt*4 + 2],
                      b1f[2*nt], b1f[2*nt+1]);
        }
        #pragma unroll
        for (int nt = 0; nt < 8; ++nt) {
            mma_fp8(accA[nt*2], accA[nt*2+1], accA[16+nt*2], accA[16+nt*2+1],
                    h0f[4], h0f[5], h0f[6], h0f[7],
                    wf[nt*4 + 1], wf[nt*4 + 3]);
            mma_fp8(accB[nt*2], accB[nt*2+1], accB[16+nt*2], accB[16+nt*2+1],
                    h1f[4], h1f[5], h1f[6], h1f[7],
                    wf[64 + nt*4 + 1], wf[64 + nt*4 + 3]);
        }

        // h0 = tanh(accA) -> fp8 frags
        tanh_to_fp8_frags(accA, h0f);

        // prefetch next-step gather into accA
        #pragma unroll
        for (int i = 0; i < 2; ++i) {
            const float* rowp = g_embW0 + tkn[i] * 64 + tq * 4;
            #pragma unroll
            for (int f = 0; f < 4; ++f) {
                float4 v = *reinterpret_cast<const float4*>(rowp + f * 16);
                accA[i * 16 + f * 4 + 0] = v.x;
                accA[i * 16 + f * 4 + 1] = v.y;
                accA[i * 16 + f * 4 + 2] = v.z;
                accA[i * 16 + f * 4 + 3] = v.w;
            }
        }

        // accB += h0new @ Wx1
        #pragma unroll
        for (int c = 0; c < 2; ++c) {
            #pragma unroll
            for (int nt = 0; nt < 8; ++nt) {
                mma_fp8(accB[nt*2], accB[nt*2+1], accB[16+nt*2], accB[16+nt*2+1],
                        h0f[c*4+0], h0f[c*4+1], h0f[c*4+2], h0f[c*4+3],
                        wf[32 + nt*4 + c], wf[32 + nt*4 + 2 + c]);
            }
        }

        // h1 = tanh(accB) -> fp8 frags
        tanh_to_fp8_frags(accB, h1f);
    }

    // ---- head: sigmoid(tanh(accB) @ Wout + bout) ----
    float wo[16];
    #pragma unroll
    for (int nt = 0; nt < 8; ++nt) {
        float2 v = *reinterpret_cast<const float2*>(Wout + nt * 8 + tq * 2);
        wo[nt * 2] = v.x; wo[nt * 2 + 1] = v.y;
    }
    float bo = bout[0];
    #pragma unroll
    for (int i = 0; i < 2; ++i) {
        float s = 0.f;
        #pragma unroll
        for (int nt = 0; nt < 8; ++nt) {
            s += fast_tanh(accB[i * 16 + nt * 2])     * wo[nt * 2];
            s += fast_tanh(accB[i * 16 + nt * 2 + 1]) * wo[nt * 2 + 1];
        }
        s += __shfl_xor_sync(0xffffffffu, s, 1);
        s += __shfl_xor_sync(0xffffffffu, s, 2);
        if (tq == 0 && rraw[i] < B)
            out[rraw[i]] = 1.0f / (1.0f + __expf(-(s + bo)));
    }
}

// ---------------------------------------------------------------------------
extern "C" void kernel_launch(void* const* d_in, const int* in_sizes, int n_in,
                              void* d_out, int out_size) {
    const int*   tokens = (const int*)  d_in[0];
    const float* emb    = (const float*)d_in[1];
    const float* Wx0    = (const float*)d_in[2];
    const float* Wh0    = (const float*)d_in[3];
    const float* b0     = (const float*)d_in[4];
    const float* Wx1    = (const float*)d_in[5];
    const float* Wh1    = (const float*)d_in[6];
    const float* b1     = (const float*)d_in[7];
    const float* Wout   = (const float*)d_in[8];
    const float* bout   = (const float*)d_in[9];
    float* out = (float*)d_out;

    int B = in_sizes[0] / SEQ;
    if (B > BMAX) B = BMAX;

    int prep_blocks = EMBW_BLOCKS + WFRAG_BLOCKS + (B + 255) / 256;
    prep_kernel<<<prep_blocks, 256>>>(emb, Wx0, b0, Wh0, Wx1, Wh1, tokens, B);

    int nblocks = (B + 15) / 16;
    rnn_kernel<<<nblocks, 32>>>(b1, Wout, bout, out, B);
}